// round 13
// baseline (speedup 1.0000x reference)
#include <cuda_runtime.h>

#define NPG   111
#define PADJ  112                 // padded M row width (28 quads)
#define HS    33                  // h row stride (conflict-free)
#define HDIM  32
#define EPG   (NPG*(NPG-1))       // 12210
#define NWARP 28
#define NTHR  (NWARP*32)          // 896
#define BGRAPHS 128

typedef unsigned long long ull;
#define FMA2(d,a,b,c) asm("fma.rn.f32x2 %0, %1, %2, %3;" : "=l"(d) : "l"(a), "l"(b), "l"(c))
#define ADD2(d,a,b)   asm("add.rn.f32x2 %0, %1, %2;" : "=l"(d) : "l"(a), "l"(b))
#define PACK2(d,lo,hi) asm("mov.b64 %0, {%1, %2};" : "=l"(d) : "f"(lo), "f"(hi))
#define UNPACK2(lo,hi,s) asm("mov.b64 {%0, %1}, %2;" : "=f"(lo), "=f"(hi) : "l"(s))

struct __align__(16) Smem {
  float Mpre[3][NPG*PADJ];          // 149184 B pre-collapsed ea.c_l; exp in place
  float feat[NPG*HDIM];             // 14208 B
  alignas(16) float h[NPG*HS+3];    // h = feat @ W (stride 33)
  alignas(16) ull   pbuf[1792];     // 14336 B Phase-B half-1 partials (f32x2)
  alignas(16) float part[22][PADJ]; // Phase-A partials / init col-sums / pool
  alignas(16) float invbuf[PADJ];
  alignas(16) float hs[PADJ];
  alignas(16) float hd[PADJ];       // hd[111]=0 pad
  alignas(16) float xs[PADJ];
  alignas(16) float asv[3][HDIM];
  alignas(16) float adv[3][HDIM];
  alignas(16) float bsh[3][HDIM];
  float w0[HDIM];
  float2 cvec[3];
  float l0s[2];
};

__device__ __forceinline__ void run_layer(Smem& S, int warp, int lane, int tid,
                                          int layer, bool relu_out,
                                          const float* __restrict__ Wg)
{
  // ---- (a) h = feat @ W (stride-33 store); hs/hd via in-warp readback ----
  if (layer == 0) {                // rank-1 (input dim 1)
    const float wl = S.w0[lane], ds = S.l0s[0], dd = S.l0s[1];
    for (int i = warp; i < NPG; i += NWARP) {
      const float xv = S.xs[i];
      S.h[i*HS + lane] = xv * wl;
      if (lane == 0) { S.hs[i] = xv*ds; S.hd[i] = xv*dd; }
    }
  } else {
    ull wp[16];                    // W[:,lane] packed consecutive-k pairs (L2)
#pragma unroll
    for (int m2 = 0; m2 < 16; ++m2)
      PACK2(wp[m2], __ldg(&Wg[(2*m2)*HDIM + lane]), __ldg(&Wg[(2*m2+1)*HDIM + lane]));
    for (int i = warp; i < NPG; i += NWARP) {
      const ulonglong2* f2 = reinterpret_cast<const ulonglong2*>(S.feat + i*HDIM);
      ull ae = 0ull, ao = 0ull;
#pragma unroll
      for (int m4 = 0; m4 < 8; ++m4) {
        const ulonglong2 f = f2[m4];           // LDS.128 broadcast
        FMA2(ae, f.x, wp[2*m4],   ae);
        FMA2(ao, f.y, wp[2*m4+1], ao);
      }
      float l0,h0,l1,h1; UNPACK2(l0,h0,ae); UNPACK2(l1,h1,ao);
      S.h[i*HS + lane] = (l0+l1) + (h0+h1);
    }
    __syncwarp();                  // warp reads back only ITS OWN rows
    {
      const int t = lane >> 3, kc = lane & 7;  // row-slot t, k-chunk kc (4 k's)
      const int row  = warp + 28*t;            // same rows as the loop above
      const int rowc = (row < NPG) ? row : NPG-1;
      const float* hr = &S.h[rowc*HS + 4*kc];  // odd stride -> bank-spread
      const float h0 = hr[0], h1 = hr[1], h2 = hr[2], h3 = hr[3];
      const float4 a4 = *reinterpret_cast<const float4*>(&S.asv[layer][4*kc]);
      const float4 d4 = *reinterpret_cast<const float4*>(&S.adv[layer][4*kc]);
      float ss = fmaf(h0,a4.x, fmaf(h1,a4.y, fmaf(h2,a4.z, h3*a4.w)));
      float sd = fmaf(h0,d4.x, fmaf(h1,d4.y, fmaf(h2,d4.z, h3*d4.w)));
#pragma unroll
      for (int o = 4; o; o >>= 1) {            // reduce over kc (3 shfl)
        ss += __shfl_xor_sync(0xffffffffu, ss, o);
        sd += __shfl_xor_sync(0xffffffffu, sd, o);
      }
      if (kc == 0 && row < NPG) { S.hs[row] = ss; S.hd[row] = sd; }
    }
  }
  __syncthreads();

  // ---- (b) Phase A: alpha -> exp in place; hs hoisted to float4 ----
  {
    float* M = S.Mpre[layer];
    const int dp = tid & 63, jc = tid >> 6;    // jc in [0,14)
    if (dp < 56) {
      const int d0 = 2*dp;
      const float hd0 = S.hd[d0], hd1 = S.hd[d0+1];
      const int j0 = jc*8;
      const float4 hsa = *reinterpret_cast<const float4*>(&S.hs[j0]);
      const float4 hsb = *reinterpret_cast<const float4*>(&S.hs[j0+4]);
      const float hsv[8] = {hsa.x,hsa.y,hsa.z,hsa.w, hsb.x,hsb.y,hsb.z,hsb.w};
      const int nj = (j0 + 8 <= NPG) ? 8 : NPG - j0;   // jc=13 -> 7
      float s0 = 0.f, s1 = 0.f;
#pragma unroll
      for (int jj = 0; jj < 8; ++jj) {
        if (jj < nj) {
          const int j = j0 + jj;
          const float2 m = *reinterpret_cast<const float2*>(&M[j*PADJ + d0]);
          float a0 = m.x + hsv[jj] + hd0;
          float a1 = m.y + hsv[jj] + hd1;
          a0 = fmaxf(a0, 0.2f*a0);             // leaky_relu
          a1 = fmaxf(a1, 0.2f*a1);
          const float e0 = __expf(a0), e1 = __expf(a1);
          *reinterpret_cast<float2*>(&M[j*PADJ + d0]) = make_float2(e0, e1);
          s0 += e0; s1 += e1;
        }
      }
      *reinterpret_cast<float2*>(&S.part[jc][d0]) = make_float2(s0, s1);
    }
  }
  __syncthreads();

  // ---- (c) Phase B: 14 groups x 8 dsts x 2 j-halves; f32x2 combine ----
  {
    const int half = warp / 14, wgrp = warp % 14;
    const ulonglong2* Mv = reinterpret_cast<const ulonglong2*>(S.Mpre[layer]);
    const int q0 = 2*wgrp, q1 = q0 + 1;
    if (half == 1 && lane < 8) {               // inv softmax sums -> SMEM
      const int d = 8*wgrp + lane;
      float s = 0.f;
#pragma unroll
      for (int k = 0; k < 14; ++k) s += S.part[k][d];
      S.invbuf[d] = 1.f / s;
    }
    const int j0 = half ? 56 : 0, j1 = half ? NPG : 56;
    ull A0=0ull, A1=0ull, A2=0ull, A3=0ull;    // dst pairs 8w..8w+7
#pragma unroll 4
    for (int j = j0; j < j1; ++j) {
      const ulonglong2 Pa = Mv[j*28 + q0];     // LDS.128 broadcast
      const ulonglong2 Pb = Mv[j*28 + q1];
      const float hv = S.h[j*HS + lane];       // 128B distinct: 1 wf
      ull hv2; PACK2(hv2, hv, hv);
      FMA2(A0, Pa.x, hv2, A0);
      FMA2(A1, Pa.y, hv2, A1);
      FMA2(A2, Pb.x, hv2, A2);
      FMA2(A3, Pb.y, hv2, A3);
    }
    const int pbase = wgrp*128 + lane;         // ull slots
    if (half == 1) {                           // dump partials (4 STS.64)
      S.pbuf[pbase+0]  = A0; S.pbuf[pbase+32] = A1;
      S.pbuf[pbase+64] = A2; S.pbuf[pbase+96] = A3;
    }
    __syncthreads();
    if (half == 0) {                           // combine + scale + store
      ull t;
      t = S.pbuf[pbase+0];  ADD2(A0, A0, t);
      t = S.pbuf[pbase+32]; ADD2(A1, A1, t);
      t = S.pbuf[pbase+64]; ADD2(A2, A2, t);
      t = S.pbuf[pbase+96]; ADD2(A3, A3, t);
      float r[8];
      UNPACK2(r[0], r[1], A0); UNPACK2(r[2], r[3], A1);
      UNPACK2(r[4], r[5], A2); UNPACK2(r[6], r[7], A3);
      const float bk = S.bsh[layer][lane];
#pragma unroll
      for (int s = 0; s < 8; ++s) {
        const int d = 8*wgrp + s;
        if (d < NPG) {
          float v = fmaf(r[s], S.invbuf[d], bk);
          if (relu_out) v = fmaxf(v, 0.f);
          S.feat[d*HDIM + lane] = v;
        }
      }
    }
  }
  __syncthreads();
}

__global__ void __launch_bounds__(NTHR, 1)
gat_fused_kernel(const float* __restrict__ x,
                 const float* __restrict__ edge_attr,
                 const float* W0, const float* as0, const float* ad0,
                 const float* We0, const float* ae0, const float* b0,
                 const float* W1, const float* as1, const float* ad1,
                 const float* We1, const float* ae1, const float* b1,
                 const float* W2, const float* as2, const float* ad2,
                 const float* We2, const float* ae2, const float* b2,
                 const float* linW, const float* linb,
                 float* __restrict__ out)
{
  extern __shared__ char smem_raw[];
  Smem& S = *reinterpret_cast<Smem*>(smem_raw);
  const int g    = blockIdx.x;
  const int tid  = threadIdx.x;
  const int warp = tid >> 5, lane = tid & 31;

  // ---- Init: small params ----
  if (tid < HDIM) {
    S.asv[0][tid]=as0[tid]; S.adv[0][tid]=ad0[tid]; S.bsh[0][tid]=b0[tid];
    S.asv[1][tid]=as1[tid]; S.adv[1][tid]=ad1[tid]; S.bsh[1][tid]=b1[tid];
    S.asv[2][tid]=as2[tid]; S.adv[2][tid]=ad2[tid]; S.bsh[2][tid]=b2[tid];
    S.w0[tid] = W0[tid];
  }
  if (warp < 6) {                  // cvec[l] = We_l @ ae_l
    const float* Wep = (warp < 2) ? We0 : (warp < 4) ? We1 : We2;
    const float* aep = (warp < 2) ? ae0 : (warp < 4) ? ae1 : ae2;
    const int l = warp >> 1, row = warp & 1;
    float p = __ldg(&Wep[row*HDIM + lane]) * __ldg(&aep[lane]);
#pragma unroll
    for (int o = 16; o; o >>= 1) p += __shfl_xor_sync(0xffffffffu, p, o);
    if (lane == 0) reinterpret_cast<float*>(&S.cvec[l])[row] = p;
  }
  if (warp == 6 || warp == 7) {    // layer-0 hs/hd scalars
    const float* av = (warp == 6) ? as0 : ad0;
    float p = __ldg(&W0[lane]) * __ldg(&av[lane]);
#pragma unroll
    for (int o = 16; o; o >>= 1) p += __shfl_xor_sync(0xffffffffu, p, o);
    if (lane == 0) S.l0s[warp - 6] = p;
  }
  if (tid < NPG) {
#pragma unroll
    for (int l = 0; l < 3; ++l) {
      S.Mpre[l][tid*PADJ + tid] = 0.f;             // diag (filled below)
      S.Mpre[l][tid*PADJ + NPG] = 0.f;             // pad column
    }
    S.xs[tid] = x[g*NPG + tid];
  }
  if (tid == NPG) S.hd[NPG] = 0.f;
  __syncthreads();

  // ---- Stream edge_attr once; scatter 3 pre-collapsed scalars (transposed) ----
  {
    const float c00=S.cvec[0].x, c01=S.cvec[0].y;
    const float c10=S.cvec[1].x, c11=S.cvec[1].y;
    const float c20=S.cvec[2].x, c21=S.cvec[2].y;
    const float2* eag = reinterpret_cast<const float2*>(edge_attr) + (size_t)g * EPG;
    for (int e = tid; e < EPG; e += NTHR) {
      const float2 v = eag[e];                     // coalesced
      const int j   = e / (NPG-1);
      const int dd0 = e - j*(NPG-1);
      const int d   = dd0 + (dd0 >= j);
      const int base = j*PADJ + d;
      S.Mpre[0][base] = fmaf(v.x, c00, v.y*c01);
      S.Mpre[1][base] = fmaf(v.x, c10, v.y*c11);
      S.Mpre[2][base] = fmaf(v.x, c20, v.y*c21);
    }
  }
  __syncthreads();

  // ---- Column sums -> diagonals (self-loop 'mean'), 3 layers fused ----
  {
    const int d = tid & 127, jc = tid >> 7;        // 7 chunks of 16 j
    if (d < PADJ) {
      const int j0 = jc*16;
      const int j1 = (j0 + 16 < NPG) ? j0 + 16 : NPG;
      float s0 = 0.f, s1 = 0.f, s2 = 0.f;
      for (int j = j0; j < j1; ++j) {
        const int o = j*PADJ + d;
        s0 += S.Mpre[0][o]; s1 += S.Mpre[1][o]; s2 += S.Mpre[2][o];
      }
      S.part[jc][d] = s0; S.part[7+jc][d] = s1; S.part[14+jc][d] = s2;
    }
    __syncthreads();
    if (tid < NPG) {
      const float inv_deg = 1.f / float(NPG-1);
#pragma unroll
      for (int l = 0; l < 3; ++l) {
        float s = 0.f;
#pragma unroll
        for (int k = 0; k < 7; ++k) s += S.part[l*7 + k][tid];
        S.Mpre[l][tid*PADJ + tid] = s * inv_deg;
      }
    }
  }
  __syncthreads();

  run_layer(S, warp, lane, tid, 0, false, W0);
  run_layer(S, warp, lane, tid, 1, true,  W1);
  run_layer(S, warp, lane, tid, 2, false, W2);

  // ---- global_add_pool + final linear + relu ----
  if (warp < 4) {
    float p = 0.f;
    for (int i = warp; i < NPG; i += 4) p += S.feat[i*HDIM + lane];
    S.part[warp][lane] = p;
  }
  __syncthreads();
  if (warp == 0) {
    const float p = S.part[0][lane] + S.part[1][lane] +
                    S.part[2][lane] + S.part[3][lane];
    float v = p * __ldg(&linW[lane]);
#pragma unroll
    for (int o = 16; o; o >>= 1) v += __shfl_xor_sync(0xffffffffu, v, o);
    if (lane == 0) out[g] = fmaxf(v + __ldg(&linb[0]), 0.f);
  }
}

extern "C" void kernel_launch(void* const* d_in, const int* in_sizes, int n_in,
                              void* d_out, int out_size) {
  (void)in_sizes; (void)n_in; (void)out_size;
  cudaFuncSetAttribute(gat_fused_kernel,
                       cudaFuncAttributeMaxDynamicSharedMemorySize,
                       (int)sizeof(Smem));
  const float* x  = (const float*)d_in[0];
  const float* ea = (const float*)d_in[2];   // d_in[1] (edge_index) structural — unused
  gat_fused_kernel<<<BGRAPHS, NTHR, sizeof(Smem)>>>(
      x, ea,
      (const float*)d_in[3],  (const float*)d_in[4],  (const float*)d_in[5],
      (const float*)d_in[6],  (const float*)d_in[7],  (const float*)d_in[8],
      (const float*)d_in[9],  (const float*)d_in[10], (const float*)d_in[11],
      (const float*)d_in[12], (const float*)d_in[13], (const float*)d_in[14],
      (const float*)d_in[15], (const float*)d_in[16], (const float*)d_in[17],
      (const float*)d_in[18], (const float*)d_in[19], (const float*)d_in[20],
      (const float*)d_in[21], (const float*)d_in[22],
      (float*)d_out);
}

// round 15
// speedup vs baseline: 1.1811x; 1.1811x over previous
#include <cuda_runtime.h>
#include <cuda_bf16.h>
#include <cstdint>

#define NPG 111
#define PADJ 112
#define HS 33
#define HDIM 32
#define EPG (NPG*(NPG-1))
#define NWARP 28
#define NTHR 896
#define BGRAPHS 128
#define AW 64                    // words per A/B tile row (128 bf16, 256B)

typedef unsigned long long ull;
#define FMA2(d,a,b,c) asm("fma.rn.f32x2 %0, %1, %2, %3;" : "=l"(d) : "l"(a), "l"(b), "l"(c))
#define PACK2(d,lo,hi) asm("mov.b64 %0, {%1, %2};" : "=l"(d) : "f"(lo), "f"(hi))
#define UNPACK2(lo,hi,s) asm("mov.b64 {%0, %1}, %2;" : "=f"(lo), "=f"(hi) : "l"(s))
#define PKBF(r,lo,hi) asm("cvt.rn.satfinite.bf16x2.f32 %0, %1, %2;" : "=r"(r) : "f"(hi), "f"(lo))
#define MMA16816(f0,f1,f2,f3,a0,a1,a2,a3,b0,b1) \
  asm volatile("mma.sync.aligned.m16n8k16.row.col.f32.bf16.bf16.f32 " \
    "{%0,%1,%2,%3}, {%4,%5,%6,%7}, {%8,%9}, {%0,%1,%2,%3};" \
    : "+f"(f0),"+f"(f1),"+f"(f2),"+f"(f3) \
    : "r"(a0),"r"(a1),"r"(a2),"r"(a3),"r"(b0),"r"(b1))

// word-swizzle within a 64-word tile row: conflict-free for 32-consecutive-row
// writers AND for (8 rows x 4 tig) fragment readers (rows 8-aligned per frag).
__device__ __forceinline__ int SWZ(int r){ return (((r)&7)<<2) | (((r)>>3)&3); }

struct __align__(16) Smem {
  float2 eaT[NPG*PADJ];                 // 99456 B; diag = per-dst mean
  alignas(16) float feat[112*HDIM];     // 14336 B, 16B-unit swizzled 128B rows
  alignas(16) float h[NPG*HS+3];        // f32 h for hs/hd readback
  alignas(16) float part[7][128];       // Phase-A col sums / pool scratch
  alignas(16) float hs[PADJ];
  alignas(16) float hd[PADJ];
  alignas(16) float xs[PADJ];
  alignas(16) float asv[3][HDIM];
  alignas(16) float adv[3][HDIM];
  alignas(16) float bsh[3][HDIM];
  alignas(16) float w0[HDIM];
  float2 cvec[3];
  float l0s[2];
  alignas(16) uint32_t Ahi[112*AW];     // 28672 B exp-weights bf16x2, d-major
  alignas(16) uint32_t Alo[112*AW];
  alignas(16) uint32_t Bhi[32*AW];      // 8192 B  hT bf16, n-major
  alignas(16) uint32_t Blo[32*AW];
};

__global__ void __launch_bounds__(NTHR, 1)
gat_fused_kernel(const float* __restrict__ x, const float* __restrict__ edge_attr,
                 const float* W0, const float* as0, const float* ad0,
                 const float* We0, const float* ae0, const float* b0,
                 const float* W1, const float* as1, const float* ad1,
                 const float* We1, const float* ae1, const float* b1,
                 const float* W2, const float* as2, const float* ad2,
                 const float* We2, const float* ae2, const float* b2,
                 const float* linW, const float* linb, float* __restrict__ out)
{
  extern __shared__ char smem_raw[];
  Smem& S = *reinterpret_cast<Smem*>(smem_raw);
  const int g = blockIdx.x, tid = threadIdx.x;
  const int warp = tid >> 5, lane = tid & 31;

  // ---- Init params ----
  if (tid < HDIM) {
    S.asv[0][tid]=as0[tid]; S.adv[0][tid]=ad0[tid]; S.bsh[0][tid]=b0[tid];
    S.asv[1][tid]=as1[tid]; S.adv[1][tid]=ad1[tid]; S.bsh[1][tid]=b1[tid];
    S.asv[2][tid]=as2[tid]; S.adv[2][tid]=ad2[tid]; S.bsh[2][tid]=b2[tid];
    S.w0[tid] = W0[tid];
    // zero B pad half-word j=111 (hi half of word 55) for all 32 n-rows
    const int w = tid*AW + (55 ^ SWZ(tid));
    *(__nv_bfloat16*)((char*)S.Bhi + w*4 + 2) = __float2bfloat16(0.f);
    *(__nv_bfloat16*)((char*)S.Blo + w*4 + 2) = __float2bfloat16(0.f);
  }
  if (tid >= 128 && tid < 192) {        // zero A row 111 (never computed)
    S.Ahi[111*AW + (tid-128)] = 0u;
    S.Alo[111*AW + (tid-128)] = 0u;
  }
  if (warp < 6) {                       // cvec[l] = We_l @ ae_l
    const float* Wep = (warp<2)?We0:(warp<4)?We1:We2;
    const float* aep = (warp<2)?ae0:(warp<4)?ae1:ae2;
    const int l = warp>>1, row = warp&1;
    float p = __ldg(&Wep[row*HDIM+lane]) * __ldg(&aep[lane]);
#pragma unroll
    for (int o=16;o;o>>=1) p += __shfl_xor_sync(0xffffffffu,p,o);
    if (lane==0) reinterpret_cast<float*>(&S.cvec[l])[row] = p;
  }
  if (warp==6 || warp==7) {             // layer-0 hs/hd scalars
    const float* av = (warp==6)?as0:ad0;
    float p = __ldg(&W0[lane]) * __ldg(&av[lane]);
#pragma unroll
    for (int o=16;o;o>>=1) p += __shfl_xor_sync(0xffffffffu,p,o);
    if (lane==0) S.l0s[warp-6] = p;
  }
  if (tid < NPG) {
    S.eaT[tid*PADJ+tid] = make_float2(0.f,0.f);
    S.eaT[tid*PADJ+NPG] = make_float2(0.f,0.f);
    S.xs[tid] = x[g*NPG+tid];
  }
  if (tid==NPG) { S.hd[NPG]=0.f; S.hs[NPG]=0.f; }
  __syncthreads();

  // ---- stream edge_attr -> transposed eaT ----
  {
    const float2* eag = reinterpret_cast<const float2*>(edge_attr) + (size_t)g*EPG;
    for (int e = tid; e < EPG; e += NTHR) {
      const float2 v = eag[e];
      const int j = e/(NPG-1), dd0 = e - j*(NPG-1), d = dd0 + (dd0>=j);
      S.eaT[j*PADJ+d] = v;
    }
  }
  __syncthreads();
  // ---- col sums -> diag = per-dst mean (feat as scratch, 14x112) ----
  {
    float* scr = S.feat;
    const int d = tid & 127, jc = tid >> 7;       // 7 chunks of 16 j
    if (d < PADJ) {
      const int j0 = jc*16, j1 = (j0+16<NPG)?j0+16:NPG;
      float sa=0.f, sb=0.f;
      for (int j=j0;j<j1;++j){ const float2 v=S.eaT[j*PADJ+d]; sa+=v.x; sb+=v.y; }
      scr[jc*PADJ+d]=sa; scr[(7+jc)*PADJ+d]=sb;
    }
    __syncthreads();
    if (tid < NPG) {
      float sa=0.f, sb=0.f;
#pragma unroll
      for (int k=0;k<7;++k){ sa+=scr[k*PADJ+tid]; sb+=scr[(7+k)*PADJ+tid]; }
      const float iv = 1.f/float(NPG-1);
      S.eaT[tid*PADJ+tid] = make_float2(sa*iv, sb*iv);
    }
  }
  __syncthreads();

  for (int layer = 0; layer < 3; ++layer) {
    const float* Wg = (layer==1) ? W1 : W2;

    // ---- (a) h = feat @ W; fill B tiles (hT bf16 hi/lo); hs/hd ----
    if (layer == 0) {
      const float wl=S.w0[lane], ds=S.l0s[0], dd=S.l0s[1];
      for (int i=warp;i<NPG;i+=NWARP){
        const float xv=S.xs[i], hv=xv*wl;
        S.h[i*HS+lane]=hv;
        const __nv_bfloat16 bh=__float2bfloat16(hv);
        const int w = lane*AW + ((i>>1) ^ SWZ(lane));
        const int byo = w*4 + (i&1)*2;
        *(__nv_bfloat16*)((char*)S.Bhi + byo) = bh;
        *(__nv_bfloat16*)((char*)S.Blo + byo) = __float2bfloat16(hv-__bfloat162float(bh));
        if (lane==0){ S.hs[i]=xv*ds; S.hd[i]=xv*dd; }
      }
    } else {
      ull wp[16];
#pragma unroll
      for (int m2=0;m2<16;++m2)
        PACK2(wp[m2], __ldg(&Wg[(2*m2)*HDIM+lane]), __ldg(&Wg[(2*m2+1)*HDIM+lane]));
      for (int i=warp;i<NPG;i+=NWARP){
        const char* fb=(const char*)S.feat + i*128; const uint32_t rx=(i&7)<<4;
        ull ae=0ull, ao=0ull;
#pragma unroll
        for (int m4=0;m4<8;++m4){
          const ulonglong2 f=*(const ulonglong2*)(fb+(((uint32_t)(m4*16))^rx));
          FMA2(ae,f.x,wp[2*m4],ae); FMA2(ao,f.y,wp[2*m4+1],ao);
        }
        float l0,h0,l1,h1; UNPACK2(l0,h0,ae); UNPACK2(l1,h1,ao);
        const float hv=(l0+l1)+(h0+h1);
        S.h[i*HS+lane]=hv;
        const __nv_bfloat16 bh=__float2bfloat16(hv);
        const int w = lane*AW + ((i>>1) ^ SWZ(lane));
        const int byo = w*4 + (i&1)*2;
        *(__nv_bfloat16*)((char*)S.Bhi + byo) = bh;
        *(__nv_bfloat16*)((char*)S.Blo + byo) = __float2bfloat16(hv-__bfloat162float(bh));
      }
      __syncwarp();
      {  // hs/hd readback over own rows; shfl unconditional
        const int t=lane>>3, kc=lane&7;
        const int row=warp+28*t, rowc=(row<NPG)?row:NPG-1;
        const float* hr=&S.h[rowc*HS+4*kc];
        const float v0=hr[0],v1=hr[1],v2=hr[2],v3=hr[3];
        const float4 a4=*(const float4*)&S.asv[layer][4*kc];
        const float4 d4=*(const float4*)&S.adv[layer][4*kc];
        float ss=fmaf(v0,a4.x,fmaf(v1,a4.y,fmaf(v2,a4.z,v3*a4.w)));
        float sd=fmaf(v0,d4.x,fmaf(v1,d4.y,fmaf(v2,d4.z,v3*d4.w)));
#pragma unroll
        for (int o=4;o;o>>=1){ ss+=__shfl_xor_sync(0xffffffffu,ss,o); sd+=__shfl_xor_sync(0xffffffffu,sd,o); }
        if (kc==0 && row<NPG){ S.hs[row]=ss; S.hd[row]=sd; }
      }
    }
    __syncthreads();

    // ---- (b) Phase A: exp -> A tiles (bf16x2 hi/lo, d-major), col sums ----
    {
      const int d = tid & 127, jc = tid >> 7;     // d row; 7 chunks of 16 j
      if (d < NPG) {
        const float c0=S.cvec[layer].x, c1=S.cvec[layer].y, hdd=S.hd[d];
        const int j0=jc*16;
        const int rowb = d*AW;
        const int sz = SWZ(d);
        float s=0.f;
#pragma unroll
        for (int t=0;t<8;++t){
          const int j=j0+2*t;
          const float2 m0=S.eaT[j*PADJ+d];
          float a0=fmaf(m0.x,c0,fmaf(m0.y,c1,S.hs[j]+hdd));
          a0=fmaxf(a0,0.2f*a0);
          const float e0=__expf(a0);
          float e1=0.f;
          if (j+1<NPG){
            const float2 m1=S.eaT[(j+1)*PADJ+d];
            float a1=fmaf(m1.x,c0,fmaf(m1.y,c1,S.hs[j+1]+hdd));
            a1=fmaxf(a1,0.2f*a1);
            e1=__expf(a1);
          }
          s += e0+e1;
          uint32_t P; PKBF(P,e0,e1);
          const int w = rowb + ((j>>1) ^ sz);
          S.Ahi[w]=P;
          const float f0=__uint_as_float(P<<16), f1=__uint_as_float(P&0xFFFF0000u);
          uint32_t Q; PKBF(Q,e0-f0,e1-f1);
          S.Alo[w]=Q;
        }
        S.part[jc][d]=s;
      }
    }
    __syncthreads();

    // ---- (c) HMMA GEMM: 28 warps = 7 mtiles x 4 ntiles; 21 mma/warp ----
    {
      const int mt = warp>>2, nt = warp&3;
      const int mb = mt*16, nb = nt*8;
      const int gid = lane>>2, tig = lane&3;
      // per-warp inverse softmax sums for its 16 rows
      float invv = 1.f;
      if (lane < 16) {
        const int d = mb + lane;
        if (d < NPG) {
          float s=0.f;
#pragma unroll
          for (int k=0;k<7;++k) s += S.part[k][d];
          invv = 1.f/s;
        }
      }
      const float i0 = __shfl_sync(0xffffffffu, invv, gid);
      const float i1 = __shfl_sync(0xffffffffu, invv, gid+8);
      const int ra0 = mb+gid, ra1 = mb+gid+8, rb = nb+gid;
      const int A0b = ra0*AW, A1b = ra1*AW, Bb = rb*AW;
      const int sA0 = SWZ(ra0), sA1 = SWZ(ra1), sB = SWZ(rb);
      float e0=0.f,e1=0.f,e2=0.f,e3=0.f;       // even-k accum
      float o0=0.f,o1=0.f,o2=0.f,o3=0.f;       // odd-k accum
#pragma unroll
      for (int k=0;k<7;++k){
        const int cb = k*8 + tig;
        const uint32_t a0h=S.Ahi[A0b+(cb^sA0)],     a1h=S.Ahi[A1b+(cb^sA1)];
        const uint32_t a2h=S.Ahi[A0b+((cb+4)^sA0)], a3h=S.Ahi[A1b+((cb+4)^sA1)];
        const uint32_t b0h=S.Bhi[Bb+(cb^sB)],       b1h=S.Bhi[Bb+((cb+4)^sB)];
        const uint32_t a0l=S.Alo[A0b+(cb^sA0)],     a1l=S.Alo[A1b+(cb^sA1)];
        const uint32_t a2l=S.Alo[A0b+((cb+4)^sA0)], a3l=S.Alo[A1b+((cb+4)^sA1)];
        const uint32_t b0l=S.Blo[Bb+(cb^sB)],       b1l=S.Blo[Bb+((cb+4)^sB)];
        if (k & 1) {
          MMA16816(o0,o1,o2,o3, a0h,a1h,a2h,a3h, b0h,b1h);
          MMA16816(o0,o1,o2,o3, a0l,a1l,a2l,a3l, b0h,b1h);
          MMA16816(o0,o1,o2,o3, a0h,a1h,a2h,a3h, b0l,b1l);
        } else {
          MMA16816(e0,e1,e2,e3, a0h,a1h,a2h,a3h, b0h,b1h);
          MMA16816(e0,e1,e2,e3, a0l,a1l,a2l,a3l, b0h,b1h);
          MMA16816(e0,e1,e2,e3, a0h,a1h,a2h,a3h, b0l,b1l);
        }
      }
      e0+=o0; e1+=o1; e2+=o2; e3+=o3;
      // epilogue: scale by 1/sum, add bias, relu(layer1), store swizzled feat
      const float bb0 = S.bsh[layer][nb+tig*2], bb1 = S.bsh[layer][nb+tig*2+1];
      const int byo = (nb + tig*2)*4;           // 8-aligned
      if (ra0 < NPG) {
        float v0 = fmaf(e0, i0, bb0), v1 = fmaf(e1, i0, bb1);
        if (layer==1){ v0=fmaxf(v0,0.f); v1=fmaxf(v1,0.f); }
        char* fb=(char*)S.feat + ra0*128;
        *(float2*)(fb + (((uint32_t)(byo & ~15)) ^ ((ra0&7)<<4)) + (byo&15)) = make_float2(v0,v1);
      }
      if (ra1 < NPG) {
        float v2 = fmaf(e2, i1, bb0), v3 = fmaf(e3, i1, bb1);
        if (layer==1){ v2=fmaxf(v2,0.f); v3=fmaxf(v3,0.f); }
        char* fb=(char*)S.feat + ra1*128;
        *(float2*)(fb + (((uint32_t)(byo & ~15)) ^ ((ra1&7)<<4)) + (byo&15)) = make_float2(v2,v3);
      }
    }
    __syncthreads();
  }

  // ---- pooling + final linear + relu (feat rows are 16B-swizzled) ----
  if (warp < 4) {
    float p = 0.f;
    for (int i=warp;i<NPG;i+=4){
      const char* fb=(const char*)S.feat + i*128;
      p += *(const float*)(fb + ((((uint32_t)(lane>>2))*16 ^ ((i&7)<<4)) + (lane&3)*4));
    }
    S.part[warp][lane] = p;
  }
  __syncthreads();
  if (warp == 0) {
    const float p = S.part[0][lane]+S.part[1][lane]+S.part[2][lane]+S.part[3][lane];
    float v = p * __ldg(&linW[lane]);
#pragma unroll
    for (int o=16;o;o>>=1) v += __shfl_xor_sync(0xffffffffu,v,o);
    if (lane==0) out[g] = fmaxf(v + __ldg(&linb[0]), 0.f);
  }
}

extern "C" void kernel_launch(void* const* d_in, const int* in_sizes, int n_in,
                              void* d_out, int out_size) {
  (void)in_sizes; (void)n_in; (void)out_size;
  cudaFuncSetAttribute(gat_fused_kernel,
                       cudaFuncAttributeMaxDynamicSharedMemorySize, (int)sizeof(Smem));
  const float* x  = (const float*)d_in[0];
  const float* ea = (const float*)d_in[2];   // d_in[1] (edge_index) structural — unused
  gat_fused_kernel<<<BGRAPHS, NTHR, sizeof(Smem)>>>(
      x, ea,
      (const float*)d_in[3],  (const float*)d_in[4],  (const float*)d_in[5],
      (const float*)d_in[6],  (const float*)d_in[7],  (const float*)d_in[8],
      (const float*)d_in[9],  (const float*)d_in[10], (const float*)d_in[11],
      (const float*)d_in[12], (const float*)d_in[13], (const float*)d_in[14],
      (const float*)d_in[15], (const float*)d_in[16], (const float*)d_in[17],
      (const float*)d_in[18], (const float*)d_in[19], (const float*)d_in[20],
      (const float*)d_in[21], (const float*)d_in[22],
      (float*)d_out);
}